// round 13
// baseline (speedup 1.0000x reference)
#include <cuda_runtime.h>

// Butterfly multiply: 16384 rows, N=2048, 11 stages, increasing stride.
// R13 = R12 (256 threads, 8 rows, 3 transposes, 2 CTAs/SM, 3 syncs,
// twiddle prefetch across barriers) with the stage-0-2 twiddle repack
// folded into the kernel: 48KB smem staging region (swizzled, conflict-free)
// replaces the separate repack kernel + g_rp global array. One launch.
//   smem: [0,48K) float4 staging for stages 0-2; [48K,112K) u64 transpose buf.

typedef unsigned long long u64;

__device__ __forceinline__ u64 d_fma2(u64 a, u64 b, u64 c) {
    u64 d; asm("fma.rn.f32x2 %0, %1, %2, %3;" : "=l"(d) : "l"(a), "l"(b), "l"(c)); return d;
}
__device__ __forceinline__ u64 d_mul2(u64 a, u64 b) {
    u64 d; asm("mul.rn.f32x2 %0, %1, %2;" : "=l"(d) : "l"(a), "l"(b)); return d;
}
__device__ __forceinline__ u64 d_bcast(float x) {
    unsigned u = __float_as_uint(x);
    u64 d; asm("mov.b64 %0, {%1, %1};" : "=l"(d) : "r"(u)); return d;
}
__device__ __forceinline__ u64 d_pack(float lo, float hi) {
    u64 d; asm("mov.b64 %0, {%1, %2};" : "=l"(d)
               : "r"(__float_as_uint(lo)), "r"(__float_as_uint(hi))); return d;
}
__device__ __forceinline__ float d_lo(u64 v) { return __uint_as_float((unsigned)(v & 0xffffffffu)); }
__device__ __forceinline__ float d_hi(u64 v) { return __uint_as_float((unsigned)(v >> 32)); }

__device__ __forceinline__ int H(int u) { return (u & 3) | (((u >> 2) & 1) << 2); }
__device__ __forceinline__ int SWZ(int s) { return s ^ ((s >> 2) & 7); }   // float4 staging swizzle

__global__ __launch_bounds__(256, 2)
void butterfly_kernel(const float* __restrict__ x,
                      const float* __restrict__ tw,
                      const float* __restrict__ bias,
                      float* __restrict__ out)
{
    extern __shared__ char smem_raw[];                       // 112 KB
    float4* g_sm = reinterpret_cast<float4*>(smem_raw);      // 3072 float4 = 48 KB
    u64*    buf  = reinterpret_cast<u64*>(smem_raw + 49152); // 8192 u64   = 64 KB

    const int t = threadIdx.x;
    const int a = t >> 3, b = t & 7;             // G1 coords
    const int c = t >> 6, d = t & 63;            // G2 coords
    const long long row0 = (long long)blockIdx.x * 8;
    const float4* tw4 = reinterpret_cast<const float4*>(tw);

    // ---- Stage 0-2 twiddles -> swizzled smem (coalesced LDG, conflict-free STS) ----
    #pragma unroll
    for (int i2 = 0; i2 < 12; ++i2) {
        const int s = 256 * i2 + t;
        g_sm[SWZ(s)] = tw4[s];
    }

    u64 v[4][8];

    // ---- Load 8 rows, elements 8t..8t+7 packed (even,odd) rows into f32x2 ----
    #pragma unroll
    for (int p = 0; p < 4; ++p) {
        const float4* ra = reinterpret_cast<const float4*>(x + (row0 + 2*p)     * 2048 + 8*t);
        const float4* rb = reinterpret_cast<const float4*>(x + (row0 + 2*p + 1) * 2048 + 8*t);
        float4 a0 = ra[0], a1 = ra[1], b0 = rb[0], b1 = rb[1];
        v[p][0] = d_pack(a0.x, b0.x); v[p][1] = d_pack(a0.y, b0.y);
        v[p][2] = d_pack(a0.z, b0.z); v[p][3] = d_pack(a0.w, b0.w);
        v[p][4] = d_pack(a1.x, b1.x); v[p][5] = d_pack(a1.y, b1.y);
        v[p][6] = d_pack(a1.z, b1.z); v[p][7] = d_pack(a1.w, b1.w);
    }

    __syncthreads();                               // staging visible (sync 0)

    #define APPLY4(T0_, T1_, T2_, T3_, J0, J1, J2, J3, DL)                           \
    {                                                                                \
        const float4 Ts[4] = { T0_, T1_, T2_, T3_ };                                 \
        const int js[4] = { J0, J1, J2, J3 };                                        \
        _Pragma("unroll")                                                            \
        for (int q = 0; q < 4; ++q) {                                                \
            const u64 T00 = d_bcast(Ts[q].x), T01 = d_bcast(Ts[q].y);                \
            const u64 T10 = d_bcast(Ts[q].z), T11 = d_bcast(Ts[q].w);                \
            const int j = js[q];                                                     \
            _Pragma("unroll")                                                        \
            for (int p = 0; p < 4; ++p) {                                            \
                const u64 lo = v[p][j], hi = v[p][j + DL];                           \
                v[p][j]      = d_fma2(T00, lo, d_mul2(T01, hi));                     \
                v[p][j + DL] = d_fma2(T10, lo, d_mul2(T11, hi));                     \
            }                                                                        \
        }                                                                            \
    }

    // ---- G0: stages 0-2, twiddle slot i at g_sm[SWZ(1024*idx + 4t + i)] ----
    {   const int s0 = 4*t;
        float4 A = g_sm[SWZ(s0+0)], B = g_sm[SWZ(s0+1)],
               C = g_sm[SWZ(s0+2)], D = g_sm[SWZ(s0+3)];
        APPLY4(A, B, C, D, 0, 2, 4, 6, 1);
    }
    {   const int s0 = 1024 + 4*t;
        float4 A = g_sm[SWZ(s0+0)], B = g_sm[SWZ(s0+1)],
               C = g_sm[SWZ(s0+2)], D = g_sm[SWZ(s0+3)];
        APPLY4(A, B, C, D, 0, 1, 4, 5, 2);
    }
    {   const int s0 = 2048 + 4*t;
        float4 A = g_sm[SWZ(s0+0)], B = g_sm[SWZ(s0+1)],
               C = g_sm[SWZ(s0+2)], D = g_sm[SWZ(s0+3)];
        APPLY4(A, B, C, D, 0, 1, 2, 3, 4);
    }

    // ---- Prefetch G1 stage-3 twiddles (hide LDG under T1 barrier) ----
    const float4* tp3 = tw4 + (3 << 10);
    float4 P0 = tp3[32*a + b],      P1 = tp3[32*a + 8 + b],
           P2 = tp3[32*a + 16 + b], P3 = tp3[32*a + 24 + b];

    // ---- Transpose T1: G0 (8t+j) -> G1 (64a+b+8j) ----
    #pragma unroll
    for (int p = 0; p < 4; ++p) {                  // 16 STS.128 back-to-back
        ulonglong2* B2 = reinterpret_cast<ulonglong2*>(buf + p * 2048);
        #pragma unroll
        for (int i = 0; i < 4; ++i) {
            const int m = 4*t + i;
            B2[m ^ H(m >> 3)] = make_ulonglong2(v[p][2*i], v[p][2*i + 1]);
        }
    }
    __syncthreads();                               // sync 1
    #pragma unroll
    for (int p = 0; p < 4; ++p)
        #pragma unroll
        for (int j = 0; j < 8; ++j) {
            const int m = 32*a + 4*j + (b >> 1);
            v[p][j] = buf[p * 2048 + 2 * (m ^ H(m >> 3)) + (b & 1)];
        }

    // ---- G1: stages 3-5, e = 64a+b+8j ----
    APPLY4(P0, P1, P2, P3, 0, 2, 4, 6, 1);         // stage 3 (prefetched)
    {   const float4* tp = tw4 + (4 << 10);
        float4 A = tp[32*a + b], B = tp[32*a + 8 + b],
               C = tp[32*a + 16 + b], D = tp[32*a + 24 + b];
        APPLY4(A, B, C, D, 0, 1, 4, 5, 2);
    }
    {   const float4* tp = tw4 + (5 << 10);
        float4 A = tp[32*a + b], B = tp[32*a + 8 + b],
               C = tp[32*a + 16 + b], D = tp[32*a + 24 + b];
        APPLY4(A, B, C, D, 0, 1, 2, 3, 4);
    }

    // ---- Prefetch G2 stage-6 twiddles ----
    const float4* tp6 = tw4 + (6 << 10);
    float4 Q0 = tp6[256*c + d],       Q1 = tp6[256*c + 64 + d],
           Q2 = tp6[256*c + 128 + d], Q3 = tp6[256*c + 192 + d];

    // ---- Transpose T2: G1 -> G2 (512c+d+64j) ----
    // No sync before store: T2-store slots == this thread's T1-load slots.
    #pragma unroll
    for (int p = 0; p < 4; ++p)
        #pragma unroll
        for (int j = 0; j < 8; ++j) {
            const int m = 32*a + 4*j + (b >> 1);
            buf[p * 2048 + 2 * (m ^ H(m >> 3)) + (b & 1)] = v[p][j];
        }
    __syncthreads();                               // sync 2
    #pragma unroll
    for (int p = 0; p < 4; ++p)
        #pragma unroll
        for (int j = 0; j < 8; ++j) {
            const int m = 256*c + 32*j + (d >> 1);
            v[p][j] = buf[p * 2048 + 2 * (m ^ H(m >> 3)) + (d & 1)];
        }

    // ---- G2: stages 6-8, e = 512c+d+64j ----
    APPLY4(Q0, Q1, Q2, Q3, 0, 2, 4, 6, 1);         // stage 6 (prefetched)
    {   const float4* tp = tw4 + (7 << 10);
        float4 A = tp[256*c + d], B = tp[256*c + 64 + d],
               C = tp[256*c + 128 + d], D = tp[256*c + 192 + d];
        APPLY4(A, B, C, D, 0, 1, 4, 5, 2);
    }
    {   const float4* tp = tw4 + (8 << 10);
        float4 A = tp[256*c + d], B = tp[256*c + 64 + d],
               C = tp[256*c + 128 + d], D = tp[256*c + 192 + d];
        APPLY4(A, B, C, D, 0, 1, 2, 3, 4);
    }

    // ---- Prefetch G3 stage-9 twiddles + bias ----
    const float4* tp9 = tw4 + (9 << 10);
    float4 R0 = tp9[t], R1 = tp9[256 + t], R2 = tp9[512 + t], R3 = tp9[768 + t];
    float bb[8];
    #pragma unroll
    for (int j = 0; j < 8; ++j) bb[j] = bias[t + 256*j];

    // ---- Transpose T3: G2 -> G3 (t+256j) ----
    // No sync before store: T3-store slots == this thread's T2-load slots.
    #pragma unroll
    for (int p = 0; p < 4; ++p)
        #pragma unroll
        for (int j = 0; j < 8; ++j) {
            const int m = 256*c + 32*j + (d >> 1);
            buf[p * 2048 + 2 * (m ^ H(m >> 3)) + (d & 1)] = v[p][j];
        }
    __syncthreads();                               // sync 3
    #pragma unroll
    for (int p = 0; p < 4; ++p)
        #pragma unroll
        for (int j = 0; j < 8; ++j) {
            const int m = 128*j + (t >> 1);
            v[p][j] = buf[p * 2048 + 2 * (m ^ H(m >> 3)) + (t & 1)];
        }

    // ---- G3: stages 9-10, e = t+256j (bias folded into stage 10) ----
    APPLY4(R0, R1, R2, R3, 0, 1, 4, 5, 2);         // stage 9 (prefetched)
    {   const float4* tp = tw4 + (10 << 10);
        #pragma unroll
        for (int j = 0; j < 4; ++j) {
            const float4 T = tp[256*j + t];
            const u64 T00 = d_bcast(T.x), T01 = d_bcast(T.y);
            const u64 T10 = d_bcast(T.z), T11 = d_bcast(T.w);
            const u64 blo = d_bcast(bb[j]), bhi = d_bcast(bb[j + 4]);
            #pragma unroll
            for (int p = 0; p < 4; ++p) {
                const u64 lo = v[p][j], hi = v[p][j + 4];
                v[p][j]     = d_fma2(T00, lo, d_fma2(T01, hi, blo));
                v[p][j + 4] = d_fma2(T10, lo, d_fma2(T11, hi, bhi));
            }
        }
    }

    // ---- Store: element t+256j of each row (coalesced) ----
    #pragma unroll
    for (int p = 0; p < 4; ++p) {
        float* oa = out + (row0 + 2*p)     * 2048;
        float* ob = out + (row0 + 2*p + 1) * 2048;
        #pragma unroll
        for (int j = 0; j < 8; ++j) {
            oa[t + 256*j] = d_lo(v[p][j]);
            ob[t + 256*j] = d_hi(v[p][j]);
        }
    }
    #undef APPLY4
}

extern "C" void kernel_launch(void* const* d_in, const int* in_sizes, int n_in,
                              void* d_out, int out_size)
{
    const float* x    = (const float*)d_in[0];
    const float* tw   = (const float*)d_in[1];
    const float* bias = (const float*)d_in[2];
    float* out        = (float*)d_out;

    const int SMEM = 49152 + 65536;   // 112 KB
    cudaFuncSetAttribute(butterfly_kernel,
                         cudaFuncAttributeMaxDynamicSharedMemorySize, SMEM);

    const int rows = in_sizes[0] / 2048;   // 16384
    butterfly_kernel<<<rows / 8, 256, SMEM>>>(x, tw, bias, out);
}

// round 16
// speedup vs baseline: 1.4101x; 1.4101x over previous
#include <cuda_runtime.h>

// Butterfly multiply: 16384 rows, N=2048, 11 stages, increasing stride.
// R14 = R12 (256 threads, 8 rows, 3 transposes, 64KB smem, 2 CTAs/SM,
// twiddle prefetch, no-sync-before-store WAR elision) with barrier scope
// reduction based on exchange locality:
//   T1 exchange is within 8-thread groups (one warp)  -> __syncwarp()
//   T2 exchange is within 64-thread groups (c = t>>6) -> bar.sync 1+c, 64
//   T3 couples the whole CTA                          -> __syncthreads()

typedef unsigned long long u64;

__device__ float4 g_rp[3072];   // repacked twiddles for stages 0-2 (48 KB)

__device__ __forceinline__ u64 d_fma2(u64 a, u64 b, u64 c) {
    u64 d; asm("fma.rn.f32x2 %0, %1, %2, %3;" : "=l"(d) : "l"(a), "l"(b), "l"(c)); return d;
}
__device__ __forceinline__ u64 d_mul2(u64 a, u64 b) {
    u64 d; asm("mul.rn.f32x2 %0, %1, %2;" : "=l"(d) : "l"(a), "l"(b)); return d;
}
__device__ __forceinline__ u64 d_bcast(float x) {
    unsigned u = __float_as_uint(x);
    u64 d; asm("mov.b64 %0, {%1, %1};" : "=l"(d) : "r"(u)); return d;
}
__device__ __forceinline__ u64 d_pack(float lo, float hi) {
    u64 d; asm("mov.b64 %0, {%1, %2};" : "=l"(d)
               : "r"(__float_as_uint(lo)), "r"(__float_as_uint(hi))); return d;
}
__device__ __forceinline__ float d_lo(u64 v) { return __uint_as_float((unsigned)(v & 0xffffffffu)); }
__device__ __forceinline__ float d_hi(u64 v) { return __uint_as_float((unsigned)(v >> 32)); }

__device__ __forceinline__ int H(int u) { return (u & 3) | (((u >> 2) & 1) << 2); }

__device__ __forceinline__ void bar64(int id) {    // 64-thread named barrier
    asm volatile("bar.sync %0, 64;" :: "r"(id) : "memory");
}

// g_rp[(idx*4 + i)*256 + t] = tw4[idx*1024 + 4t + i]
__global__ void repack_kernel(const float4* __restrict__ tw4) {
    int dst = blockIdx.x * 256 + threadIdx.x;          // 0..3071
    int idx = dst >> 10, r = dst & 1023, i = r >> 8, t = r & 255;
    g_rp[dst] = tw4[idx * 1024 + 4 * t + i];
}

__global__ __launch_bounds__(256, 2)
void butterfly_kernel(const float* __restrict__ x,
                      const float* __restrict__ tw,
                      const float* __restrict__ bias,
                      float* __restrict__ out)
{
    extern __shared__ u64 buf[];                 // 4 * 2048 u64 = 64 KB
    const int t = threadIdx.x;
    const int a = t >> 3, b = t & 7;             // G1 coords
    const int c = t >> 6, d = t & 63;            // G2 coords
    const long long row0 = (long long)blockIdx.x * 8;
    const float4* tw4 = reinterpret_cast<const float4*>(tw);

    u64 v[4][8];

    // ---- Load 8 rows, elements 8t..8t+7 packed (even,odd) rows into f32x2 ----
    #pragma unroll
    for (int p = 0; p < 4; ++p) {
        const float4* ra = reinterpret_cast<const float4*>(x + (row0 + 2*p)     * 2048 + 8*t);
        const float4* rb = reinterpret_cast<const float4*>(x + (row0 + 2*p + 1) * 2048 + 8*t);
        float4 a0 = ra[0], a1 = ra[1], b0 = rb[0], b1 = rb[1];
        v[p][0] = d_pack(a0.x, b0.x); v[p][1] = d_pack(a0.y, b0.y);
        v[p][2] = d_pack(a0.z, b0.z); v[p][3] = d_pack(a0.w, b0.w);
        v[p][4] = d_pack(a1.x, b1.x); v[p][5] = d_pack(a1.y, b1.y);
        v[p][6] = d_pack(a1.z, b1.z); v[p][7] = d_pack(a1.w, b1.w);
    }

    #define APPLY4(T0_, T1_, T2_, T3_, J0, J1, J2, J3, DL)                           \
    {                                                                                \
        const float4 Ts[4] = { T0_, T1_, T2_, T3_ };                                 \
        const int js[4] = { J0, J1, J2, J3 };                                        \
        _Pragma("unroll")                                                            \
        for (int q = 0; q < 4; ++q) {                                                \
            const u64 T00 = d_bcast(Ts[q].x), T01 = d_bcast(Ts[q].y);                \
            const u64 T10 = d_bcast(Ts[q].z), T11 = d_bcast(Ts[q].w);                \
            const int j = js[q];                                                     \
            _Pragma("unroll")                                                        \
            for (int p = 0; p < 4; ++p) {                                            \
                const u64 lo = v[p][j], hi = v[p][j + DL];                           \
                v[p][j]      = d_fma2(T00, lo, d_mul2(T01, hi));                     \
                v[p][j + DL] = d_fma2(T10, lo, d_mul2(T11, hi));                     \
            }                                                                        \
        }                                                                            \
    }

    // ---- G0: stages 0-2 via repacked scratch (fully coalesced) ----
    {   float4 A = g_rp[0*256 + t], B = g_rp[1*256 + t],
               C = g_rp[2*256 + t], D = g_rp[3*256 + t];
        APPLY4(A, B, C, D, 0, 2, 4, 6, 1);
    }
    {   float4 A = g_rp[4*256 + t], B = g_rp[5*256 + t],
               C = g_rp[6*256 + t], D = g_rp[7*256 + t];
        APPLY4(A, B, C, D, 0, 1, 4, 5, 2);
    }
    {   float4 A = g_rp[8*256 + t], B = g_rp[9*256 + t],
               C = g_rp[10*256 + t], D = g_rp[11*256 + t];
        APPLY4(A, B, C, D, 0, 1, 2, 3, 4);
    }

    // ---- Prefetch G1 stage-3 twiddles ----
    const float4* tp3 = tw4 + (3 << 10);
    float4 P0 = tp3[32*a + b],      P1 = tp3[32*a + 8 + b],
           P2 = tp3[32*a + 16 + b], P3 = tp3[32*a + 24 + b];

    // ---- Transpose T1: G0 (8t+j) -> G1 (64a+b+8j) ----
    // Exchange is block-diagonal in 8-thread groups (threads 8a..8a+7,
    // always within one warp) -> __syncwarp() is sufficient.
    #pragma unroll
    for (int p = 0; p < 4; ++p) {                  // 16 STS.128 back-to-back
        ulonglong2* B2 = reinterpret_cast<ulonglong2*>(buf + p * 2048);
        #pragma unroll
        for (int i = 0; i < 4; ++i) {
            const int m = 4*t + i;
            B2[m ^ H(m >> 3)] = make_ulonglong2(v[p][2*i], v[p][2*i + 1]);
        }
    }
    __syncwarp();                                  // was full __syncthreads
    #pragma unroll
    for (int p = 0; p < 4; ++p)
        #pragma unroll
        for (int j = 0; j < 8; ++j) {
            const int m = 32*a + 4*j + (b >> 1);
            v[p][j] = buf[p * 2048 + 2 * (m ^ H(m >> 3)) + (b & 1)];
        }

    // ---- G1: stages 3-5, e = 64a+b+8j ----
    APPLY4(P0, P1, P2, P3, 0, 2, 4, 6, 1);         // stage 3 (prefetched)
    {   const float4* tp = tw4 + (4 << 10);
        float4 A = tp[32*a + b], B = tp[32*a + 8 + b],
               C = tp[32*a + 16 + b], D = tp[32*a + 24 + b];
        APPLY4(A, B, C, D, 0, 1, 4, 5, 2);
    }
    {   const float4* tp = tw4 + (5 << 10);
        float4 A = tp[32*a + b], B = tp[32*a + 8 + b],
               C = tp[32*a + 16 + b], D = tp[32*a + 24 + b];
        APPLY4(A, B, C, D, 0, 1, 2, 3, 4);
    }

    // ---- Prefetch G2 stage-6 twiddles ----
    const float4* tp6 = tw4 + (6 << 10);
    float4 Q0 = tp6[256*c + d],       Q1 = tp6[256*c + 64 + d],
           Q2 = tp6[256*c + 128 + d], Q3 = tp6[256*c + 192 + d];

    // ---- Transpose T2: G1 -> G2 (512c+d+64j) ----
    // No sync before store (same-thread WAR with T1 load slots).
    // Exchange is block-diagonal in c = t>>6 (64-thread groups, 2 warps)
    // -> named 64-thread barrier instead of full __syncthreads.
    #pragma unroll
    for (int p = 0; p < 4; ++p)
        #pragma unroll
        for (int j = 0; j < 8; ++j) {
            const int m = 32*a + 4*j + (b >> 1);
            buf[p * 2048 + 2 * (m ^ H(m >> 3)) + (b & 1)] = v[p][j];
        }
    bar64(1 + c);                                  // was full __syncthreads
    #pragma unroll
    for (int p = 0; p < 4; ++p)
        #pragma unroll
        for (int j = 0; j < 8; ++j) {
            const int m = 256*c + 32*j + (d >> 1);
            v[p][j] = buf[p * 2048 + 2 * (m ^ H(m >> 3)) + (d & 1)];
        }

    // ---- G2: stages 6-8, e = 512c+d+64j ----
    APPLY4(Q0, Q1, Q2, Q3, 0, 2, 4, 6, 1);         // stage 6 (prefetched)
    {   const float4* tp = tw4 + (7 << 10);
        float4 A = tp[256*c + d], B = tp[256*c + 64 + d],
               C = tp[256*c + 128 + d], D = tp[256*c + 192 + d];
        APPLY4(A, B, C, D, 0, 1, 4, 5, 2);
    }
    {   const float4* tp = tw4 + (8 << 10);
        float4 A = tp[256*c + d], B = tp[256*c + 64 + d],
               C = tp[256*c + 128 + d], D = tp[256*c + 192 + d];
        APPLY4(A, B, C, D, 0, 1, 2, 3, 4);
    }

    // ---- Prefetch G3 stage-9 twiddles + bias ----
    const float4* tp9 = tw4 + (9 << 10);
    float4 R0 = tp9[t], R1 = tp9[256 + t], R2 = tp9[512 + t], R3 = tp9[768 + t];
    float bb[8];
    #pragma unroll
    for (int j = 0; j < 8; ++j) bb[j] = bias[t + 256*j];

    // ---- Transpose T3: G2 -> G3 (t+256j) ----
    // No sync before store (same-thread WAR with T2 load slots).
    // Full-CTA exchange -> __syncthreads.
    #pragma unroll
    for (int p = 0; p < 4; ++p)
        #pragma unroll
        for (int j = 0; j < 8; ++j) {
            const int m = 256*c + 32*j + (d >> 1);
            buf[p * 2048 + 2 * (m ^ H(m >> 3)) + (d & 1)] = v[p][j];
        }
    __syncthreads();
    #pragma unroll
    for (int p = 0; p < 4; ++p)
        #pragma unroll
        for (int j = 0; j < 8; ++j) {
            const int m = 128*j + (t >> 1);
            v[p][j] = buf[p * 2048 + 2 * (m ^ H(m >> 3)) + (t & 1)];
        }

    // ---- G3: stages 9-10, e = t+256j (bias folded into stage 10) ----
    APPLY4(R0, R1, R2, R3, 0, 1, 4, 5, 2);         // stage 9 (prefetched)
    {   const float4* tp = tw4 + (10 << 10);
        #pragma unroll
        for (int j = 0; j < 4; ++j) {
            const float4 T = tp[256*j + t];
            const u64 T00 = d_bcast(T.x), T01 = d_bcast(T.y);
            const u64 T10 = d_bcast(T.z), T11 = d_bcast(T.w);
            const u64 blo = d_bcast(bb[j]), bhi = d_bcast(bb[j + 4]);
            #pragma unroll
            for (int p = 0; p < 4; ++p) {
                const u64 lo = v[p][j], hi = v[p][j + 4];
                v[p][j]     = d_fma2(T00, lo, d_fma2(T01, hi, blo));
                v[p][j + 4] = d_fma2(T10, lo, d_fma2(T11, hi, bhi));
            }
        }
    }

    // ---- Store: element t+256j of each row (coalesced) ----
    #pragma unroll
    for (int p = 0; p < 4; ++p) {
        float* oa = out + (row0 + 2*p)     * 2048;
        float* ob = out + (row0 + 2*p + 1) * 2048;
        #pragma unroll
        for (int j = 0; j < 8; ++j) {
            oa[t + 256*j] = d_lo(v[p][j]);
            ob[t + 256*j] = d_hi(v[p][j]);
        }
    }
    #undef APPLY4
}

extern "C" void kernel_launch(void* const* d_in, const int* in_sizes, int n_in,
                              void* d_out, int out_size)
{
    const float* x    = (const float*)d_in[0];
    const float* tw   = (const float*)d_in[1];
    const float* bias = (const float*)d_in[2];
    float* out        = (float*)d_out;

    cudaFuncSetAttribute(butterfly_kernel,
                         cudaFuncAttributeMaxDynamicSharedMemorySize, 65536);

    repack_kernel<<<12, 256>>>(reinterpret_cast<const float4*>(tw));
    const int rows = in_sizes[0] / 2048;   // 16384
    butterfly_kernel<<<rows / 8, 256, 65536>>>(x, tw, bias, out);
}

// round 17
// speedup vs baseline: 1.4255x; 1.0109x over previous
#include <cuda_runtime.h>

// Butterfly multiply: 16384 rows, N=2048, 11 stages, increasing stride.
// R17 = R16 (256 threads, 8 rows, 3 transposes, 64KB smem, 2 CTAs/SM,
// twiddle prefetch, WAR elision, scoped barriers) with the last FULL
// __syncthreads (T3) replaced by parity-split 4-warp named barriers:
//   T3 exchange couples only warps of equal parity h=(t>>5)&1
//   (store warp parity of element e == load warp parity == (e>>5)&1),
//   so bar.sync 5+h, 128 suffices. No CTA-wide barrier remains.
//   T1 -> __syncwarp(); T2 -> bar.sync 1+c, 64; T3 -> bar.sync 5+h, 128.

typedef unsigned long long u64;

__device__ float4 g_rp[3072];   // repacked twiddles for stages 0-2 (48 KB)

__device__ __forceinline__ u64 d_fma2(u64 a, u64 b, u64 c) {
    u64 d; asm("fma.rn.f32x2 %0, %1, %2, %3;" : "=l"(d) : "l"(a), "l"(b), "l"(c)); return d;
}
__device__ __forceinline__ u64 d_mul2(u64 a, u64 b) {
    u64 d; asm("mul.rn.f32x2 %0, %1, %2;" : "=l"(d) : "l"(a), "l"(b)); return d;
}
__device__ __forceinline__ u64 d_bcast(float x) {
    unsigned u = __float_as_uint(x);
    u64 d; asm("mov.b64 %0, {%1, %1};" : "=l"(d) : "r"(u)); return d;
}
__device__ __forceinline__ u64 d_pack(float lo, float hi) {
    u64 d; asm("mov.b64 %0, {%1, %2};" : "=l"(d)
               : "r"(__float_as_uint(lo)), "r"(__float_as_uint(hi))); return d;
}
__device__ __forceinline__ float d_lo(u64 v) { return __uint_as_float((unsigned)(v & 0xffffffffu)); }
__device__ __forceinline__ float d_hi(u64 v) { return __uint_as_float((unsigned)(v >> 32)); }

__device__ __forceinline__ int H(int u) { return (u & 3) | (((u >> 2) & 1) << 2); }

__device__ __forceinline__ void bar_n(int id, int nthreads) {
    asm volatile("bar.sync %0, %1;" :: "r"(id), "r"(nthreads) : "memory");
}

// g_rp[(idx*4 + i)*256 + t] = tw4[idx*1024 + 4t + i]
__global__ void repack_kernel(const float4* __restrict__ tw4) {
    int dst = blockIdx.x * 256 + threadIdx.x;          // 0..3071
    int idx = dst >> 10, r = dst & 1023, i = r >> 8, t = r & 255;
    g_rp[dst] = tw4[idx * 1024 + 4 * t + i];
}

__global__ __launch_bounds__(256, 2)
void butterfly_kernel(const float* __restrict__ x,
                      const float* __restrict__ tw,
                      const float* __restrict__ bias,
                      float* __restrict__ out)
{
    extern __shared__ u64 buf[];                 // 4 * 2048 u64 = 64 KB
    const int t = threadIdx.x;
    const int a = t >> 3, b = t & 7;             // G1 coords
    const int c = t >> 6, d = t & 63;            // G2 coords
    const int h = (t >> 5) & 1;                  // T3 warp-parity group
    const long long row0 = (long long)blockIdx.x * 8;
    const float4* tw4 = reinterpret_cast<const float4*>(tw);

    u64 v[4][8];

    // ---- Load 8 rows, elements 8t..8t+7 packed (even,odd) rows into f32x2 ----
    #pragma unroll
    for (int p = 0; p < 4; ++p) {
        const float4* ra = reinterpret_cast<const float4*>(x + (row0 + 2*p)     * 2048 + 8*t);
        const float4* rb = reinterpret_cast<const float4*>(x + (row0 + 2*p + 1) * 2048 + 8*t);
        float4 a0 = ra[0], a1 = ra[1], b0 = rb[0], b1 = rb[1];
        v[p][0] = d_pack(a0.x, b0.x); v[p][1] = d_pack(a0.y, b0.y);
        v[p][2] = d_pack(a0.z, b0.z); v[p][3] = d_pack(a0.w, b0.w);
        v[p][4] = d_pack(a1.x, b1.x); v[p][5] = d_pack(a1.y, b1.y);
        v[p][6] = d_pack(a1.z, b1.z); v[p][7] = d_pack(a1.w, b1.w);
    }

    #define APPLY4(T0_, T1_, T2_, T3_, J0, J1, J2, J3, DL)                           \
    {                                                                                \
        const float4 Ts[4] = { T0_, T1_, T2_, T3_ };                                 \
        const int js[4] = { J0, J1, J2, J3 };                                        \
        _Pragma("unroll")                                                            \
        for (int q = 0; q < 4; ++q) {                                                \
            const u64 T00 = d_bcast(Ts[q].x), T01 = d_bcast(Ts[q].y);                \
            const u64 T10 = d_bcast(Ts[q].z), T11 = d_bcast(Ts[q].w);                \
            const int j = js[q];                                                     \
            _Pragma("unroll")                                                        \
            for (int p = 0; p < 4; ++p) {                                            \
                const u64 lo = v[p][j], hi = v[p][j + DL];                           \
                v[p][j]      = d_fma2(T00, lo, d_mul2(T01, hi));                     \
                v[p][j + DL] = d_fma2(T10, lo, d_mul2(T11, hi));                     \
            }                                                                        \
        }                                                                            \
    }

    // ---- G0: stages 0-2 via repacked scratch (fully coalesced) ----
    {   float4 A = g_rp[0*256 + t], B = g_rp[1*256 + t],
               C = g_rp[2*256 + t], D = g_rp[3*256 + t];
        APPLY4(A, B, C, D, 0, 2, 4, 6, 1);
    }
    {   float4 A = g_rp[4*256 + t], B = g_rp[5*256 + t],
               C = g_rp[6*256 + t], D = g_rp[7*256 + t];
        APPLY4(A, B, C, D, 0, 1, 4, 5, 2);
    }
    {   float4 A = g_rp[8*256 + t], B = g_rp[9*256 + t],
               C = g_rp[10*256 + t], D = g_rp[11*256 + t];
        APPLY4(A, B, C, D, 0, 1, 2, 3, 4);
    }

    // ---- Prefetch G1 stage-3 twiddles ----
    const float4* tp3 = tw4 + (3 << 10);
    float4 P0 = tp3[32*a + b],      P1 = tp3[32*a + 8 + b],
           P2 = tp3[32*a + 16 + b], P3 = tp3[32*a + 24 + b];

    // ---- Transpose T1: G0 (8t+j) -> G1 (64a+b+8j) ----
    // Exchange within 8-thread groups (one warp) -> __syncwarp().
    #pragma unroll
    for (int p = 0; p < 4; ++p) {                  // 16 STS.128 back-to-back
        ulonglong2* B2 = reinterpret_cast<ulonglong2*>(buf + p * 2048);
        #pragma unroll
        for (int i = 0; i < 4; ++i) {
            const int m = 4*t + i;
            B2[m ^ H(m >> 3)] = make_ulonglong2(v[p][2*i], v[p][2*i + 1]);
        }
    }
    __syncwarp();
    #pragma unroll
    for (int p = 0; p < 4; ++p)
        #pragma unroll
        for (int j = 0; j < 8; ++j) {
            const int m = 32*a + 4*j + (b >> 1);
            v[p][j] = buf[p * 2048 + 2 * (m ^ H(m >> 3)) + (b & 1)];
        }

    // ---- G1: stages 3-5, e = 64a+b+8j ----
    APPLY4(P0, P1, P2, P3, 0, 2, 4, 6, 1);         // stage 3 (prefetched)
    {   const float4* tp = tw4 + (4 << 10);
        float4 A = tp[32*a + b], B = tp[32*a + 8 + b],
               C = tp[32*a + 16 + b], D = tp[32*a + 24 + b];
        APPLY4(A, B, C, D, 0, 1, 4, 5, 2);
    }
    {   const float4* tp = tw4 + (5 << 10);
        float4 A = tp[32*a + b], B = tp[32*a + 8 + b],
               C = tp[32*a + 16 + b], D = tp[32*a + 24 + b];
        APPLY4(A, B, C, D, 0, 1, 2, 3, 4);
    }

    // ---- Prefetch G2 stage-6 twiddles ----
    const float4* tp6 = tw4 + (6 << 10);
    float4 Q0 = tp6[256*c + d],       Q1 = tp6[256*c + 64 + d],
           Q2 = tp6[256*c + 128 + d], Q3 = tp6[256*c + 192 + d];

    // ---- Transpose T2: G1 -> G2 (512c+d+64j) ----
    // No sync before store (same-thread WAR with T1 load slots).
    // Exchange block-diagonal in c (2 contiguous warps) -> bar.sync 1+c, 64.
    #pragma unroll
    for (int p = 0; p < 4; ++p)
        #pragma unroll
        for (int j = 0; j < 8; ++j) {
            const int m = 32*a + 4*j + (b >> 1);
            buf[p * 2048 + 2 * (m ^ H(m >> 3)) + (b & 1)] = v[p][j];
        }
    bar_n(1 + c, 64);
    #pragma unroll
    for (int p = 0; p < 4; ++p)
        #pragma unroll
        for (int j = 0; j < 8; ++j) {
            const int m = 256*c + 32*j + (d >> 1);
            v[p][j] = buf[p * 2048 + 2 * (m ^ H(m >> 3)) + (d & 1)];
        }

    // ---- G2: stages 6-8, e = 512c+d+64j ----
    APPLY4(Q0, Q1, Q2, Q3, 0, 2, 4, 6, 1);         // stage 6 (prefetched)
    {   const float4* tp = tw4 + (7 << 10);
        float4 A = tp[256*c + d], B = tp[256*c + 64 + d],
               C = tp[256*c + 128 + d], D = tp[256*c + 192 + d];
        APPLY4(A, B, C, D, 0, 1, 4, 5, 2);
    }
    {   const float4* tp = tw4 + (8 << 10);
        float4 A = tp[256*c + d], B = tp[256*c + 64 + d],
               C = tp[256*c + 128 + d], D = tp[256*c + 192 + d];
        APPLY4(A, B, C, D, 0, 1, 2, 3, 4);
    }

    // ---- Prefetch G3 stage-9 twiddles + bias ----
    const float4* tp9 = tw4 + (9 << 10);
    float4 R0 = tp9[t], R1 = tp9[256 + t], R2 = tp9[512 + t], R3 = tp9[768 + t];
    float bb[8];
    #pragma unroll
    for (int j = 0; j < 8; ++j) bb[j] = bias[t + 256*j];

    // ---- Transpose T3: G2 -> G3 (t+256j) ----
    // No sync before store (same-thread WAR with T2 load slots).
    // Element e: store-thread warp parity == load-thread warp parity ==
    // (e>>5)&1, so the exchange couples only equal-parity warps
    // {h, h+2, h+4, h+6} -> parity-split 128-thread named barrier.
    #pragma unroll
    for (int p = 0; p < 4; ++p)
        #pragma unroll
        for (int j = 0; j < 8; ++j) {
            const int m = 256*c + 32*j + (d >> 1);
            buf[p * 2048 + 2 * (m ^ H(m >> 3)) + (d & 1)] = v[p][j];
        }
    bar_n(5 + h, 128);
    #pragma unroll
    for (int p = 0; p < 4; ++p)
        #pragma unroll
        for (int j = 0; j < 8; ++j) {
            const int m = 128*j + (t >> 1);
            v[p][j] = buf[p * 2048 + 2 * (m ^ H(m >> 3)) + (t & 1)];
        }

    // ---- G3: stages 9-10, e = t+256j (bias folded into stage 10) ----
    APPLY4(R0, R1, R2, R3, 0, 1, 4, 5, 2);         // stage 9 (prefetched)
    {   const float4* tp = tw4 + (10 << 10);
        #pragma unroll
        for (int j = 0; j < 4; ++j) {
            const float4 T = tp[256*j + t];
            const u64 T00 = d_bcast(T.x), T01 = d_bcast(T.y);
            const u64 T10 = d_bcast(T.z), T11 = d_bcast(T.w);
            const u64 blo = d_bcast(bb[j]), bhi = d_bcast(bb[j + 4]);
            #pragma unroll
            for (int p = 0; p < 4; ++p) {
                const u64 lo = v[p][j], hi = v[p][j + 4];
                v[p][j]     = d_fma2(T00, lo, d_fma2(T01, hi, blo));
                v[p][j + 4] = d_fma2(T10, lo, d_fma2(T11, hi, bhi));
            }
        }
    }

    // ---- Store: element t+256j of each row (coalesced) ----
    #pragma unroll
    for (int p = 0; p < 4; ++p) {
        float* oa = out + (row0 + 2*p)     * 2048;
        float* ob = out + (row0 + 2*p + 1) * 2048;
        #pragma unroll
        for (int j = 0; j < 8; ++j) {
            oa[t + 256*j] = d_lo(v[p][j]);
            ob[t + 256*j] = d_hi(v[p][j]);
        }
    }
    #undef APPLY4
}

extern "C" void kernel_launch(void* const* d_in, const int* in_sizes, int n_in,
                              void* d_out, int out_size)
{
    const float* x    = (const float*)d_in[0];
    const float* tw   = (const float*)d_in[1];
    const float* bias = (const float*)d_in[2];
    float* out        = (float*)d_out;

    cudaFuncSetAttribute(butterfly_kernel,
                         cudaFuncAttributeMaxDynamicSharedMemorySize, 65536);

    repack_kernel<<<12, 256>>>(reinterpret_cast<const float4*>(tw));
    const int rows = in_sizes[0] / 2048;   // 16384
    butterfly_kernel<<<rows / 8, 256, 65536>>>(x, tw, bias, out);
}